// round 13
// baseline (speedup 1.0000x reference)
#include <cuda_runtime.h>
#include <cuda_fp16.h>
#include <cstdint>
#include <cstddef>

#define BB 8
#define TT 40
#define HH 32
#define WW 32
#define CC 64
#define THREADS 128

typedef unsigned int u32;

// Slab (single, fp16): 449 slots (14 h-rows x 32 w + 1 zero slot), 32 ci fp16 = 64B
// data + 16B pad -> stride 80B (16B-aligned ldmatrix rows; 8-row phases conflict-free).
// Slab rows: 0..5 = center t (h0-1..h0+4), 6..9 = t-1 (h0..h0+3), 10..13 = t+1.
#define SSTR 80
#define NSLOT 448
#define ZSLOT 448
#define SM_B   ((NSLOT + 1) * SSTR)          // 35920: B-fragment table (smem-resident)
#define NBFRAG (7 * 2 * 2 * 32)              // [tap][ks][pb][lane] uint4 = 896 entries
#define SM_TOTAL (SM_B + NBFRAG * 16)        // 50256 B -> 4 CTAs/SM

// B fragments precomputed in ldmatrix-output order, single fp16 limb:
// g_btbl[tap][ks][pb][lane] = uint4 of matrices i=0..3:
//   co=(pb*2+(i>>1))*8+(lane>>2), ci pair = ks*16+(i&1)*8+2*(lane&3) (+0,+1),
//   packed fp16x2 low-half-first.
// Taps: 0:t-1 1:t+1 2:h-1 3:center(sum) 4:h+1 5:w-1 6:w+1
__device__ __align__(16) uint4 g_btbl[NBFRAG];   // 14336 B

__device__ __forceinline__ float getw(int tap, int co, int ci,
                                      const float* wT, const float* wH, const float* wW) {
    int si = ci * 32 + co;            // source [kt][ci][co]
    switch (tap) {
        case 0: return wT[si];
        case 1: return wT[2048 + si];
        case 2: return wH[si];
        case 3: return wT[1024 + si] + wH[1024 + si] + wW[1024 + si];
        case 4: return wH[2048 + si];
        case 5: return wW[si];
        default: return wW[2048 + si];
    }
}

__global__ void prep_w(const float* __restrict__ wT,
                       const float* __restrict__ wH,
                       const float* __restrict__ wW) {
    int tap  = blockIdx.x;                       // 7 blocks x 128 threads
    int tx   = threadIdx.x;
    int ks   = tx >> 6;
    int pb   = (tx >> 5) & 1;
    int lane = tx & 31;

    u32 comp[4];
#pragma unroll
    for (int c = 0; c < 4; ++c) {                // c = matrix index i
        int co  = (pb * 2 + (c >> 1)) * 8 + (lane >> 2);
        int ci0 = ks * 16 + (c & 1) * 8 + 2 * (lane & 3);
        __half p0 = __float2half_rn(getw(tap, co, ci0,     wT, wH, wW));
        __half p1 = __float2half_rn(getw(tap, co, ci0 + 1, wT, wH, wW));
        comp[c] = ((u32)__half_as_ushort(p1) << 16) | (u32)__half_as_ushort(p0);
    }
    g_btbl[((tap * 2 + ks) * 2 + pb) * 32 + lane] = make_uint4(comp[0], comp[1], comp[2], comp[3]);
}

__device__ __forceinline__ void ldsm4(u32 addr, u32& r0, u32& r1, u32& r2, u32& r3) {
    asm volatile("ldmatrix.sync.aligned.m8n8.x4.shared.b16 {%0,%1,%2,%3}, [%4];"
                 : "=r"(r0), "=r"(r1), "=r"(r2), "=r"(r3) : "r"(addr));
}
__device__ __forceinline__ void mma16816(float d[4], const u32 a[4], const u32 b[2]) {
    asm volatile(
        "mma.sync.aligned.m16n8k16.row.col.f32.f16.f16.f32 "
        "{%0,%1,%2,%3}, {%4,%5,%6,%7}, {%8,%9}, {%0,%1,%2,%3};"
        : "+f"(d[0]), "+f"(d[1]), "+f"(d[2]), "+f"(d[3])
        : "r"(a[0]), "r"(a[1]), "r"(a[2]), "r"(a[3]), "r"(b[0]), "r"(b[1]));
}

__global__ __launch_bounds__(THREADS, 4)
void mvf_mma(const float* __restrict__ x, float* __restrict__ out) {
    extern __shared__ char smem[];
    const int tid  = threadIdx.x;
    const int lane = tid & 31;
    const int wid  = tid >> 5;

    const int bx  = blockIdx.x;
    const int hc  = bx & 7;
    const int tmp = bx >> 3;
    const int t   = tmp % TT;
    const int b   = tmp / TT;
    const int h0  = hc * 4;

    // ---- fill slab: x rounded to fp16 (single A limb; B single limb too) ----
    for (int j = tid; j < NSLOT * 8; j += THREADS) {
        int q = j & 7, slot = j >> 3, r = slot >> 5, w = slot & 31;
        int tp, h;
        if (r < 6)       { tp = t;     h = h0 - 1 + r;  }
        else if (r < 10) { tp = t - 1; h = h0 + r - 6;  }
        else             { tp = t + 1; h = h0 + r - 10; }
        float4 v = make_float4(0.f, 0.f, 0.f, 0.f);
        if ((unsigned)tp < TT && (unsigned)h < HH)
            v = __ldg((const float4*)(x + ((((size_t)b * TT + tp) * HH + h) * WW + w) * CC) + q);
        union { __half2 h2[2]; uint2 u; } ph;
        ph.h2[0] = __floats2half2_rn(v.x, v.y);
        ph.h2[1] = __floats2half2_rn(v.z, v.w);
        *(uint2*)(smem + slot * SSTR + q * 8) = ph.u;
    }
    // zero slot (80B)
    if (tid < 10)
        ((uint2*)(smem + ZSLOT * SSTR))[tid] = make_uint2(0u, 0u);

    // ---- B-fragment table -> smem (896 uint4, 7 per thread, coalesced) ----
    for (int j = tid; j < NBFRAG; j += THREADS)
        *(uint4*)(smem + SM_B + j * 16) = __ldg(&g_btbl[j]);

    // ---- skip-channel passthrough ----
    {
        int r = tid >> 5, w = tid & 31;
        size_t gi = ((((size_t)b * TT + t) * HH + h0 + r) * WW + w) * CC + 32;
        const float4* s4 = (const float4*)(x + gi);
        float4* d4 = (float4*)(out + gi);
#pragma unroll
        for (int q = 0; q < 8; ++q) d4[q] = s4[q];
    }

    __syncthreads();

    // ---- compute: warp = h-row (h0+wid) x 32 w x 32 co ----
    const u32 sbase = (u32)__cvta_generic_to_shared(smem);

    // A ldmatrix lane roles: x4 = (m0-7,k0-7),(m8-15,k0-7),(m0-7,k8-15),(m8-15,k8-15)
    const int amat   = lane >> 3, ar = lane & 7;
    const int a_mloc = (amat & 1) * 8 + ar;       // m row within m16
    const int a_kb   = (amat >> 1) * 16;          // k byte offset

    int sb[7], dw[7];
    sb[0] = 6 + wid;  dw[0] = 0;    // t-1
    sb[1] = 10 + wid; dw[1] = 0;    // t+1
    sb[2] = wid;      dw[2] = 0;    // h-1
    sb[3] = wid + 1;  dw[3] = 0;    // center
    sb[4] = wid + 2;  dw[4] = 0;    // h+1
    sb[5] = wid + 1;  dw[5] = -1;   // w-1
    sb[6] = wid + 1;  dw[6] = 1;    // w+1

    float D[2][4][4];
#pragma unroll
    for (int mt = 0; mt < 2; ++mt)
#pragma unroll
        for (int nb = 0; nb < 4; ++nb)
#pragma unroll
            for (int k = 0; k < 4; ++k) D[mt][nb][k] = 0.f;

#pragma unroll
    for (int tap = 0; tap < 7; ++tap) {
        // B fragments: 4 x LDS.128 from the smem-resident table
        u32 Bf[2][4][2];
#pragma unroll
        for (int ks = 0; ks < 2; ++ks)
#pragma unroll
            for (int pb = 0; pb < 2; ++pb) {
                uint4 v = *(const uint4*)(smem + SM_B +
                          (((tap * 2 + ks) * 2 + pb) * 32 + lane) * 16);
                Bf[ks][pb * 2][0]     = v.x; Bf[ks][pb * 2][1]     = v.y;
                Bf[ks][pb * 2 + 1][0] = v.z; Bf[ks][pb * 2 + 1][1] = v.w;
            }
#pragma unroll
        for (int mt = 0; mt < 2; ++mt) {
            int wsrc = mt * 16 + a_mloc + dw[tap];
            int slot = ((unsigned)wsrc < WW) ? sb[tap] * 32 + wsrc : ZSLOT;
            u32 abase = (u32)(slot * SSTR + a_kb);
#pragma unroll
            for (int ks = 0; ks < 2; ++ks) {
                u32 Ah[4];
                ldsm4(sbase + abase + ks * 32, Ah[0], Ah[1], Ah[2], Ah[3]);
#pragma unroll
                for (int nb = 0; nb < 4; ++nb)
                    mma16816(D[mt][nb], Ah, Bf[ks][nb]);
            }
        }
    }

    // ---- epilogue: ReLU + store (c0,c1 at row grp; c2,c3 at row grp+8) ----
    const int grp = lane >> 2, qd = lane & 3;
    const size_t rowbase = (((size_t)b * TT + t) * HH + h0 + wid) * WW;
#pragma unroll
    for (int mt = 0; mt < 2; ++mt)
#pragma unroll
        for (int nb = 0; nb < 4; ++nb)
#pragma unroll
            for (int hr = 0; hr < 2; ++hr) {
                int wpos = mt * 16 + hr * 8 + grp;
                int co = nb * 8 + qd * 2;
                float2 v;
                v.x = fmaxf(D[mt][nb][hr * 2 + 0], 0.f);
                v.y = fmaxf(D[mt][nb][hr * 2 + 1], 0.f);
                *(float2*)(out + (rowbase + wpos) * CC + co) = v;
            }
}

extern "C" void kernel_launch(void* const* d_in, const int* in_sizes, int n_in,
                              void* d_out, int out_size) {
    const float* x  = (const float*)d_in[0];
    const float* wT = (const float*)d_in[1];
    const float* wH = (const float*)d_in[2];
    const float* wW = (const float*)d_in[3];
    float* out = (float*)d_out;

    prep_w<<<7, 128>>>(wT, wH, wW);

    cudaFuncSetAttribute(mvf_mma, cudaFuncAttributeMaxDynamicSharedMemorySize, SM_TOTAL);
    mvf_mma<<<BB * TT * 8, THREADS, SM_TOTAL>>>(x, out);
}

// round 15
// speedup vs baseline: 1.1341x; 1.1341x over previous
#include <cuda_runtime.h>
#include <cuda_fp16.h>
#include <cstdint>
#include <cstddef>

#define BB 8
#define TT 40
#define HH 32
#define WW 32
#define CC 64
#define THREADS 128

typedef unsigned int u32;

// Slab (single, fp16): 449 slots (14 h-rows x 32 w + 1 zero slot), 32 ci fp16 = 64B
// data + 16B pad -> stride 80B (16B-aligned ldmatrix rows; 8-row phases conflict-free).
// Slab rows: 0..5 = center t (h0-1..h0+4), 6..9 = t-1 (h0..h0+3), 10..13 = t+1.
#define SSTR 80
#define NSLOT 448
#define ZSLOT 448
#define SM_B   ((NSLOT + 1) * SSTR)          // 35920: B-fragment table (smem-resident)
#define NBFRAG (7 * 2 * 2 * 32)              // [tap][ks][pb][lane] uint4 = 896 entries
#define SM_TOTAL (SM_B + NBFRAG * 16)        // 50256 B -> 4 CTAs/SM

// B fragments precomputed in ldmatrix-output order, single fp16 limb:
// g_btbl[tap][ks][pb][lane] = uint4 of matrices i=0..3:
//   co=(pb*2+(i>>1))*8+(lane>>2), ci pair = ks*16+(i&1)*8+2*(lane&3) (+0,+1),
//   packed fp16x2 low-half-first.
// Taps: 0:t-1 1:t+1 2:h-1 3:center(sum) 4:h+1 5:w-1 6:w+1
__device__ __align__(16) uint4 g_btbl[NBFRAG];   // 14336 B

__device__ __forceinline__ float getw(int tap, int co, int ci,
                                      const float* wT, const float* wH, const float* wW) {
    int si = ci * 32 + co;            // source [kt][ci][co]
    switch (tap) {
        case 0: return wT[si];
        case 1: return wT[2048 + si];
        case 2: return wH[si];
        case 3: return wT[1024 + si] + wH[1024 + si] + wW[1024 + si];
        case 4: return wH[2048 + si];
        case 5: return wW[si];
        default: return wW[2048 + si];
    }
}

__global__ void prep_w(const float* __restrict__ wT,
                       const float* __restrict__ wH,
                       const float* __restrict__ wW) {
    int tap  = blockIdx.x;                       // 7 blocks x 128 threads
    int tx   = threadIdx.x;
    int ks   = tx >> 6;
    int pb   = (tx >> 5) & 1;
    int lane = tx & 31;

    u32 comp[4];
#pragma unroll
    for (int c = 0; c < 4; ++c) {                // c = matrix index i
        int co  = (pb * 2 + (c >> 1)) * 8 + (lane >> 2);
        int ci0 = ks * 16 + (c & 1) * 8 + 2 * (lane & 3);
        __half p0 = __float2half_rn(getw(tap, co, ci0,     wT, wH, wW));
        __half p1 = __float2half_rn(getw(tap, co, ci0 + 1, wT, wH, wW));
        comp[c] = ((u32)__half_as_ushort(p1) << 16) | (u32)__half_as_ushort(p0);
    }
    g_btbl[((tap * 2 + ks) * 2 + pb) * 32 + lane] = make_uint4(comp[0], comp[1], comp[2], comp[3]);
}

__device__ __forceinline__ void ldsm4(u32 addr, u32& r0, u32& r1, u32& r2, u32& r3) {
    asm volatile("ldmatrix.sync.aligned.m8n8.x4.shared.b16 {%0,%1,%2,%3}, [%4];"
                 : "=r"(r0), "=r"(r1), "=r"(r2), "=r"(r3) : "r"(addr));
}
__device__ __forceinline__ void mma16816(float d[4], const u32 a[4], const u32 b[2]) {
    asm volatile(
        "mma.sync.aligned.m16n8k16.row.col.f32.f16.f16.f32 "
        "{%0,%1,%2,%3}, {%4,%5,%6,%7}, {%8,%9}, {%0,%1,%2,%3};"
        : "+f"(d[0]), "+f"(d[1]), "+f"(d[2]), "+f"(d[3])
        : "r"(a[0]), "r"(a[1]), "r"(a[2]), "r"(a[3]), "r"(b[0]), "r"(b[1]));
}

__global__ __launch_bounds__(THREADS, 4)
void mvf_mma(const float* __restrict__ x, float* __restrict__ out) {
    extern __shared__ char smem[];
    const int tid  = threadIdx.x;
    const int lane = tid & 31;
    const int wid  = tid >> 5;

    const int bx  = blockIdx.x;
    const int hc  = bx & 7;
    const int tmp = bx >> 3;
    const int t   = tmp % TT;
    const int b   = tmp / TT;
    const int h0  = hc * 4;

    // ---- fill slab with batched high-MLP loads ----
    // Thread tid owns q = tid&7, slots s0+16k for k=0..27 (s0 = tid>>3).
    // 4 batches of 7: issue 7 independent predicated LDG.128, then convert+STS.
    {
        const int q  = tid & 7;
        const int s0 = tid >> 3;
#pragma unroll
        for (int bch = 0; bch < 4; ++bch) {
            float4 vv[7];
#pragma unroll
            for (int u = 0; u < 7; ++u) {
                int slot = s0 + (bch * 7 + u) * 16;
                int r = slot >> 5, w = slot & 31;
                int tp, h;
                if (r < 6)       { tp = t;     h = h0 - 1 + r;  }
                else if (r < 10) { tp = t - 1; h = h0 + r - 6;  }
                else             { tp = t + 1; h = h0 + r - 10; }
                bool ok = ((unsigned)tp < TT) && ((unsigned)h < HH);
                const float4* p = (const float4*)(x +
                    ((((size_t)b * TT + (ok ? tp : 0)) * HH + (ok ? h : 0)) * WW + w) * CC) + q;
                float4 v = __ldg(p);
                vv[u].x = ok ? v.x : 0.f; vv[u].y = ok ? v.y : 0.f;
                vv[u].z = ok ? v.z : 0.f; vv[u].w = ok ? v.w : 0.f;
            }
#pragma unroll
            for (int u = 0; u < 7; ++u) {
                int slot = s0 + (bch * 7 + u) * 16;
                union { __half2 h2[2]; uint2 uu; } ph;
                ph.h2[0] = __floats2half2_rn(vv[u].x, vv[u].y);
                ph.h2[1] = __floats2half2_rn(vv[u].z, vv[u].w);
                *(uint2*)(smem + slot * SSTR + q * 8) = ph.uu;
            }
        }
    }
    // zero slot (80B)
    if (tid < 10)
        ((uint2*)(smem + ZSLOT * SSTR))[tid] = make_uint2(0u, 0u);

    // ---- B-fragment table -> smem (896 uint4, 7 per thread, coalesced) ----
    for (int j = tid; j < NBFRAG; j += THREADS)
        *(uint4*)(smem + SM_B + j * 16) = __ldg(&g_btbl[j]);

    // ---- skip-channel passthrough ----
    {
        int r = tid >> 5, w = tid & 31;
        size_t gi = ((((size_t)b * TT + t) * HH + h0 + r) * WW + w) * CC + 32;
        const float4* s4 = (const float4*)(x + gi);
        float4* d4 = (float4*)(out + gi);
        float4 tmpv[8];
#pragma unroll
        for (int q = 0; q < 8; ++q) tmpv[q] = __ldg(s4 + q);   // batch loads (MLP 8)
#pragma unroll
        for (int q = 0; q < 8; ++q) d4[q] = tmpv[q];
    }

    __syncthreads();

    // ---- compute: warp = h-row (h0+wid) x 32 w x 32 co ----
    const u32 sbase = (u32)__cvta_generic_to_shared(smem);

    // A ldmatrix lane roles: x4 = (m0-7,k0-7),(m8-15,k0-7),(m0-7,k8-15),(m8-15,k8-15)
    const int amat   = lane >> 3, ar = lane & 7;
    const int a_mloc = (amat & 1) * 8 + ar;       // m row within m16
    const int a_kb   = (amat >> 1) * 16;          // k byte offset

    int sb[7], dw[7];
    sb[0] = 6 + wid;  dw[0] = 0;    // t-1
    sb[1] = 10 + wid; dw[1] = 0;    // t+1
    sb[2] = wid;      dw[2] = 0;    // h-1
    sb[3] = wid + 1;  dw[3] = 0;    // center
    sb[4] = wid + 2;  dw[4] = 0;    // h+1
    sb[5] = wid + 1;  dw[5] = -1;   // w-1
    sb[6] = wid + 1;  dw[6] = 1;    // w+1

    float D[2][4][4];
#pragma unroll
    for (int mt = 0; mt < 2; ++mt)
#pragma unroll
        for (int nb = 0; nb < 4; ++nb)
#pragma unroll
            for (int k = 0; k < 4; ++k) D[mt][nb][k] = 0.f;

#pragma unroll
    for (int tap = 0; tap < 7; ++tap) {
        // hoist ALL loads for this tap first: 4 B LDS.128 + 4 A ldsm.x4
        u32 Bf[2][4][2];
#pragma unroll
        for (int ks = 0; ks < 2; ++ks)
#pragma unroll
            for (int pb = 0; pb < 2; ++pb) {
                uint4 v = *(const uint4*)(smem + SM_B +
                          (((tap * 2 + ks) * 2 + pb) * 32 + lane) * 16);
                Bf[ks][pb * 2][0]     = v.x; Bf[ks][pb * 2][1]     = v.y;
                Bf[ks][pb * 2 + 1][0] = v.z; Bf[ks][pb * 2 + 1][1] = v.w;
            }
        u32 Af[2][2][4];
#pragma unroll
        for (int mt = 0; mt < 2; ++mt) {
            int wsrc = mt * 16 + a_mloc + dw[tap];
            int slot = ((unsigned)wsrc < WW) ? sb[tap] * 32 + wsrc : ZSLOT;
            u32 abase = (u32)(slot * SSTR + a_kb);
#pragma unroll
            for (int ks = 0; ks < 2; ++ks)
                ldsm4(sbase + abase + ks * 32,
                      Af[mt][ks][0], Af[mt][ks][1], Af[mt][ks][2], Af[mt][ks][3]);
        }
        // 16-mma burst
#pragma unroll
        for (int mt = 0; mt < 2; ++mt)
#pragma unroll
            for (int ks = 0; ks < 2; ++ks)
#pragma unroll
                for (int nb = 0; nb < 4; ++nb)
                    mma16816(D[mt][nb], Af[mt][ks], Bf[ks][nb]);
    }

    // ---- epilogue: ReLU + store (c0,c1 at row grp; c2,c3 at row grp+8) ----
    const int grp = lane >> 2, qd = lane & 3;
    const size_t rowbase = (((size_t)b * TT + t) * HH + h0 + wid) * WW;
#pragma unroll
    for (int mt = 0; mt < 2; ++mt)
#pragma unroll
        for (int nb = 0; nb < 4; ++nb)
#pragma unroll
            for (int hr = 0; hr < 2; ++hr) {
                int wpos = mt * 16 + hr * 8 + grp;
                int co = nb * 8 + qd * 2;
                float2 v;
                v.x = fmaxf(D[mt][nb][hr * 2 + 0], 0.f);
                v.y = fmaxf(D[mt][nb][hr * 2 + 1], 0.f);
                *(float2*)(out + (rowbase + wpos) * CC + co) = v;
            }
}

extern "C" void kernel_launch(void* const* d_in, const int* in_sizes, int n_in,
                              void* d_out, int out_size) {
    const float* x  = (const float*)d_in[0];
    const float* wT = (const float*)d_in[1];
    const float* wH = (const float*)d_in[2];
    const float* wW = (const float*)d_in[3];
    float* out = (float*)d_out;

    prep_w<<<7, 128>>>(wT, wH, wW);

    cudaFuncSetAttribute(mvf_mma, cudaFuncAttributeMaxDynamicSharedMemorySize, SM_TOTAL);
    mvf_mma<<<BB * TT * 8, THREADS, SM_TOTAL>>>(x, out);
}

// round 16
// speedup vs baseline: 1.3797x; 1.2165x over previous
#include <cuda_runtime.h>
#include <cuda_fp16.h>
#include <cstdint>
#include <cstddef>

#define BB 8
#define TT 40
#define HH 32
#define WW 32
#define CC 64
#define THREADS 256

typedef unsigned int u32;

// Slab (single, fp16): 641 slots (20 rows x 32 w + 1 zero slot), 32 ci fp16 = 64B
// data + 16B pad -> stride 80B (16B-aligned ldmatrix rows; conflict-free phases).
// Rows (outputs t0 and t0+1, h-tile h0..h0+3):
//   0..3   : plane t0-1, h0..h0+3
//   4..9   : plane t0,   h0-1..h0+4
//   10..15 : plane t0+1, h0-1..h0+4
//   16..19 : plane t0+2, h0..h0+3
#define SSTR 80
#define NROWS 20
#define NSLOT (NROWS * 32)                   // 640
#define ZSLOT NSLOT
#define SM_B   ((NSLOT + 1) * SSTR)          // 51280: B-fragment table (smem-resident)
#define NBFRAG (7 * 2 * 2 * 32)              // [tap][ks][pb][lane] uint4 = 896 entries
#define SM_TOTAL (SM_B + NBFRAG * 16)        // 65616 B -> 2 CTAs/SM @ 256 thr (16 warps)

// B fragments precomputed in ldmatrix-output order, single fp16 limb:
// g_btbl[tap][ks][pb][lane] = uint4 of matrices i=0..3:
//   co=(pb*2+(i>>1))*8+(lane>>2), ci pair = ks*16+(i&1)*8+2*(lane&3) (+0,+1),
//   packed fp16x2 low-half-first.
// Taps: 0:t-1 1:t+1 2:h-1 3:center(sum) 4:h+1 5:w-1 6:w+1
__device__ __align__(16) uint4 g_btbl[NBFRAG];   // 14336 B

__device__ __forceinline__ float getw(int tap, int co, int ci,
                                      const float* wT, const float* wH, const float* wW) {
    int si = ci * 32 + co;            // source [kt][ci][co]
    switch (tap) {
        case 0: return wT[si];
        case 1: return wT[2048 + si];
        case 2: return wH[si];
        case 3: return wT[1024 + si] + wH[1024 + si] + wW[1024 + si];
        case 4: return wH[2048 + si];
        case 5: return wW[si];
        default: return wW[2048 + si];
    }
}

__global__ void prep_w(const float* __restrict__ wT,
                       const float* __restrict__ wH,
                       const float* __restrict__ wW) {
    int tap  = blockIdx.x;                       // 7 blocks x 128 threads
    int tx   = threadIdx.x;
    int ks   = tx >> 6;
    int pb   = (tx >> 5) & 1;
    int lane = tx & 31;

    u32 comp[4];
#pragma unroll
    for (int c = 0; c < 4; ++c) {                // c = matrix index i
        int co  = (pb * 2 + (c >> 1)) * 8 + (lane >> 2);
        int ci0 = ks * 16 + (c & 1) * 8 + 2 * (lane & 3);
        __half p0 = __float2half_rn(getw(tap, co, ci0,     wT, wH, wW));
        __half p1 = __float2half_rn(getw(tap, co, ci0 + 1, wT, wH, wW));
        comp[c] = ((u32)__half_as_ushort(p1) << 16) | (u32)__half_as_ushort(p0);
    }
    g_btbl[((tap * 2 + ks) * 2 + pb) * 32 + lane] = make_uint4(comp[0], comp[1], comp[2], comp[3]);
}

__device__ __forceinline__ void ldsm4(u32 addr, u32& r0, u32& r1, u32& r2, u32& r3) {
    asm volatile("ldmatrix.sync.aligned.m8n8.x4.shared.b16 {%0,%1,%2,%3}, [%4];"
                 : "=r"(r0), "=r"(r1), "=r"(r2), "=r"(r3) : "r"(addr));
}
__device__ __forceinline__ void mma16816(float d[4], const u32 a[4], const u32 b[2]) {
    asm volatile(
        "mma.sync.aligned.m16n8k16.row.col.f32.f16.f16.f32 "
        "{%0,%1,%2,%3}, {%4,%5,%6,%7}, {%8,%9}, {%0,%1,%2,%3};"
        : "+f"(d[0]), "+f"(d[1]), "+f"(d[2]), "+f"(d[3])
        : "r"(a[0]), "r"(a[1]), "r"(a[2]), "r"(a[3]), "r"(b[0]), "r"(b[1]));
}

__global__ __launch_bounds__(THREADS, 2)
void mvf_mma(const float* __restrict__ x, float* __restrict__ out) {
    extern __shared__ char smem[];
    const int tid  = threadIdx.x;
    const int lane = tid & 31;
    const int wid  = tid >> 5;            // 0..7

    const int bx  = blockIdx.x;
    const int hc  = bx & 7;
    const int tmp = bx >> 3;
    const int tp2 = tmp % (TT / 2);
    const int b   = tmp / (TT / 2);
    const int t0  = tp2 * 2;
    const int h0  = hc * 4;

    // ---- fill slab: thread owns w = tid>>3, q = tid&7, rows 0..19 ----
    // 4 batches of 5 independent predicated LDG.128 (MLP 5), then convert+STS.
    {
        const int q = tid & 7;
        const int w = tid >> 3;           // 0..31
#pragma unroll
        for (int bch = 0; bch < 4; ++bch) {
            float4 vv[5];
#pragma unroll
            for (int u = 0; u < 5; ++u) {
                int r = bch * 5 + u;      // slab row 0..19
                int tp, h;
                if (r < 4)       { tp = t0 - 1; h = h0 + r;       }
                else if (r < 10) { tp = t0;     h = h0 - 1 + (r - 4);  }
                else if (r < 16) { tp = t0 + 1; h = h0 - 1 + (r - 10); }
                else             { tp = t0 + 2; h = h0 + (r - 16);     }
                bool ok = ((unsigned)tp < TT) && ((unsigned)h < HH);
                const float4* p = (const float4*)(x +
                    ((((size_t)b * TT + (ok ? tp : 0)) * HH + (ok ? h : 0)) * WW + w) * CC) + q;
                float4 v = __ldg(p);
                vv[u].x = ok ? v.x : 0.f; vv[u].y = ok ? v.y : 0.f;
                vv[u].z = ok ? v.z : 0.f; vv[u].w = ok ? v.w : 0.f;
            }
#pragma unroll
            for (int u = 0; u < 5; ++u) {
                int slot = (bch * 5 + u) * 32 + w;
                union { __half2 h2[2]; uint2 uu; } ph;
                ph.h2[0] = __floats2half2_rn(vv[u].x, vv[u].y);
                ph.h2[1] = __floats2half2_rn(vv[u].z, vv[u].w);
                *(uint2*)(smem + slot * SSTR + q * 8) = ph.uu;
            }
        }
    }
    // zero slot (80B)
    if (tid < 10)
        ((uint2*)(smem + ZSLOT * SSTR))[tid] = make_uint2(0u, 0u);

    // ---- B-fragment table -> smem (896 uint4, coalesced) ----
    for (int j = tid; j < NBFRAG; j += THREADS)
        *(uint4*)(smem + SM_B + j * 16) = __ldg(&g_btbl[j]);

    // ---- skip-channel passthrough: 2 tiles x 4 rows x 32 w = 256 positions ----
    {
        int g = tid >> 7, r = (tid >> 5) & 3, w = tid & 31;
        size_t gi = ((((size_t)b * TT + t0 + g) * HH + h0 + r) * WW + w) * CC + 32;
        const float4* s4 = (const float4*)(x + gi);
        float4* d4 = (float4*)(out + gi);
        float4 tmpv[8];
#pragma unroll
        for (int q = 0; q < 8; ++q) tmpv[q] = __ldg(s4 + q);
#pragma unroll
        for (int q = 0; q < 8; ++q) d4[q] = tmpv[q];
    }

    __syncthreads();

    // ---- compute: warpgroup g = wid>>2 -> output t0+g; widh = wid&3 -> h-row ----
    const u32 sbase = (u32)__cvta_generic_to_shared(smem);
    const int g    = wid >> 2;
    const int widh = wid & 3;
    const int cb   = 4 + 6 * g;           // center-plane base row (h0-1)

    // A ldmatrix lane roles: x4 = (m0-7,k0-7),(m8-15,k0-7),(m0-7,k8-15),(m8-15,k8-15)
    const int amat   = lane >> 3, ar = lane & 7;
    const int a_mloc = (amat & 1) * 8 + ar;
    const int a_kb   = (amat >> 1) * 16;

    int sb[7], dw[7];
    sb[0] = g ? (5 + widh) : widh;         dw[0] = 0;   // t-1 tap
    sb[1] = g ? (16 + widh) : (11 + widh); dw[1] = 0;   // t+1 tap
    sb[2] = cb + widh;                     dw[2] = 0;   // h-1
    sb[3] = cb + widh + 1;                 dw[3] = 0;   // center
    sb[4] = cb + widh + 2;                 dw[4] = 0;   // h+1
    sb[5] = cb + widh + 1;                 dw[5] = -1;  // w-1
    sb[6] = cb + widh + 1;                 dw[6] = 1;   // w+1

    float D[2][4][4];
#pragma unroll
    for (int mt = 0; mt < 2; ++mt)
#pragma unroll
        for (int nb = 0; nb < 4; ++nb)
#pragma unroll
            for (int k = 0; k < 4; ++k) D[mt][nb][k] = 0.f;

#pragma unroll
    for (int tap = 0; tap < 7; ++tap) {
        // hoist ALL loads for this tap: 4 B LDS.128 + 4 A ldsm.x4
        u32 Bf[2][4][2];
#pragma unroll
        for (int ks = 0; ks < 2; ++ks)
#pragma unroll
            for (int pb = 0; pb < 2; ++pb) {
                uint4 v = *(const uint4*)(smem + SM_B +
                          (((tap * 2 + ks) * 2 + pb) * 32 + lane) * 16);
                Bf[ks][pb * 2][0]     = v.x; Bf[ks][pb * 2][1]     = v.y;
                Bf[ks][pb * 2 + 1][0] = v.z; Bf[ks][pb * 2 + 1][1] = v.w;
            }
        u32 Af[2][2][4];
#pragma unroll
        for (int mt = 0; mt < 2; ++mt) {
            int wsrc = mt * 16 + a_mloc + dw[tap];
            int slot = ((unsigned)wsrc < WW) ? sb[tap] * 32 + wsrc : ZSLOT;
            u32 abase = (u32)(slot * SSTR + a_kb);
#pragma unroll
            for (int ks = 0; ks < 2; ++ks)
                ldsm4(sbase + abase + ks * 32,
                      Af[mt][ks][0], Af[mt][ks][1], Af[mt][ks][2], Af[mt][ks][3]);
        }
        // 16-mma burst
#pragma unroll
        for (int mt = 0; mt < 2; ++mt)
#pragma unroll
            for (int ks = 0; ks < 2; ++ks)
#pragma unroll
                for (int nb = 0; nb < 4; ++nb)
                    mma16816(D[mt][nb], Af[mt][ks], Bf[ks][nb]);
    }

    // ---- epilogue: ReLU + store (c0,c1 at row grp; c2,c3 at row grp+8) ----
    const int grp = lane >> 2, qd = lane & 3;
    const size_t rowbase = (((size_t)b * TT + t0 + g) * HH + h0 + widh) * WW;
#pragma unroll
    for (int mt = 0; mt < 2; ++mt)
#pragma unroll
        for (int nb = 0; nb < 4; ++nb)
#pragma unroll
            for (int hr = 0; hr < 2; ++hr) {
                int wpos = mt * 16 + hr * 8 + grp;
                int co = nb * 8 + qd * 2;
                float2 v;
                v.x = fmaxf(D[mt][nb][hr * 2 + 0], 0.f);
                v.y = fmaxf(D[mt][nb][hr * 2 + 1], 0.f);
                *(float2*)(out + (rowbase + wpos) * CC + co) = v;
            }
}

extern "C" void kernel_launch(void* const* d_in, const int* in_sizes, int n_in,
                              void* d_out, int out_size) {
    const float* x  = (const float*)d_in[0];
    const float* wT = (const float*)d_in[1];
    const float* wH = (const float*)d_in[2];
    const float* wW = (const float*)d_in[3];
    float* out = (float*)d_out;

    prep_w<<<7, 128>>>(wT, wH, wW);

    cudaFuncSetAttribute(mvf_mma, cudaFuncAttributeMaxDynamicSharedMemorySize, SM_TOTAL);
    mvf_mma<<<BB * (TT / 2) * 8, THREADS, SM_TOTAL>>>(x, out);
}